// round 4
// baseline (speedup 1.0000x reference)
#include <cuda_runtime.h>
#include <cstdint>

// ---------------------------------------------------------------------------
// C3 layer: x(128,6,256,256) -> out(128,16,252,252), 5x5 VALID convs.
// Direct conv. Each thread: 4 horizontal pixels x 8 output channels.
// The 16 oc are split into two balanced groups chosen by threadIdx.z
// (warp-uniform). FFMA2 (fma.rn.f32x2) accumulators; weights in smem as
// duplicated (w,w) pairs at compile-time-constant offsets.
// 3 CTAs/SM (launch_bounds) for latency hiding.
// ---------------------------------------------------------------------------

__device__ constexpr int POC[6][10] = {
    {0, 4, 5, 6,  9, 10, 11, 12, 14, 15},
    {0, 1, 5, 6,  7, 10, 11, 12, 13, 15},
    {0, 1, 2, 6,  7,  8, 11, 13, 14, 15},
    {1, 2, 3, 6,  7,  8,  9, 12, 14, 15},
    {2, 3, 4, 7,  8,  9, 10, 12, 13, 15},
    {3, 4, 5, 8,  9, 10, 11, 13, 14, 15}
};
__device__ constexpr int POFF[6][10] = {
    {  0, 300, 375, 450, 750,  850,  950, 1050, 1250, 1350},
    { 25,  75, 400, 475, 550,  875,  975, 1075, 1150, 1375},
    { 50, 100, 150, 500, 575,  650, 1000, 1175, 1275, 1400},
    {125, 175, 225, 525, 600,  675,  775, 1100, 1300, 1425},
    {200, 250, 325, 625, 700,  800,  900, 1125, 1200, 1450},
    {275, 350, 425, 725, 825,  925, 1025, 1225, 1325, 1475}
};

// Two balanced oc groups (29 vs 31 channel-pairs).
__device__ constexpr int OCS[2][8] = {
    {0, 1, 2, 3, 4, 6, 7, 15},
    {5, 8, 9, 10, 11, 12, 13, 14}
};
// oc -> accumulator slot within group (-1 = not in group).
__device__ constexpr int GSLOT[2][16] = {
    { 0,  1,  2,  3,  4, -1,  5,  6, -1, -1, -1, -1, -1, -1, -1,  7},
    {-1, -1, -1, -1, -1,  0, -1, -1,  1,  2,  3,  4,  5,  6,  7, -1}
};

#define FMA2(acc, a, b) asm("fma.rn.f32x2 %0, %1, %2, %0;" : "+l"(acc) : "l"(a), "l"(b))

__device__ __forceinline__ unsigned long long pack2(float lo, float hi) {
    unsigned long long r;
    asm("mov.b64 %0, {%1, %2};" : "=l"(r) : "f"(lo), "f"(hi));
    return r;
}

union F4 {
    float4 f;
    unsigned long long u[2];
};
union F2 {
    float2 f;
    unsigned long long u;
};

template <int G>
__device__ __forceinline__ void compute_group(
    const float* __restrict__ x, float* __restrict__ out,
    const float* __restrict__ wsm, const float* __restrict__ bsm,
    int b, int p, int q0, int ql)
{
    unsigned long long accL[8], accH[8];
    #pragma unroll
    for (int s = 0; s < 8; ++s) {
        float bv = bsm[OCS[G][s]];
        accL[s] = pack2(bv, bv);
        accH[s] = accL[s];
    }

    #pragma unroll
    for (int c = 0; c < 6; ++c) {
        const float* xp = x + (((size_t)b * 6 + c) * 256 + p) * 256 + ql;
        #pragma unroll
        for (int ky = 0; ky < 5; ++ky) {
            F4 a0, a1;
            a0.f = *(const float4*)(xp + ky * 256);
            a1.f = *(const float4*)(xp + ky * 256 + 4);

            unsigned long long V01 = a0.u[0];
            unsigned long long V23 = a0.u[1];
            unsigned long long V45 = a1.u[0];
            unsigned long long V67 = a1.u[1];
            unsigned long long V12 = pack2(a0.f.y, a0.f.z);
            unsigned long long V34 = pack2(a0.f.w, a1.f.x);
            unsigned long long V56 = pack2(a1.f.y, a1.f.z);

            #pragma unroll
            for (int j = 0; j < 10; ++j) {
                const int oc = POC[c][j];
                const int s  = GSLOT[G][oc];
                if (s >= 0) {
                    const int base = (((c * 10 + j) * 5 + ky) * 12);
                    F4 wA; wA.f = *(const float4*)&wsm[base];      // W0, W1
                    F4 wB; wB.f = *(const float4*)&wsm[base + 4];  // W2, W3
                    F2 wC; wC.f = *(const float2*)&wsm[base + 8];  // W4

                    FMA2(accL[s], wA.u[0], V01);  FMA2(accH[s], wA.u[0], V23);
                    FMA2(accL[s], wA.u[1], V12);  FMA2(accH[s], wA.u[1], V34);
                    FMA2(accL[s], wB.u[0], V23);  FMA2(accH[s], wB.u[0], V45);
                    FMA2(accL[s], wB.u[1], V34);  FMA2(accH[s], wB.u[1], V56);
                    FMA2(accL[s], wC.u,    V45);  FMA2(accH[s], wC.u,    V67);
                }
            }
        }
    }

    if (q0 < 252) {
        #pragma unroll
        for (int s = 0; s < 8; ++s) {
            const int oc = OCS[G][s];
            F4 r;
            r.u[0] = accL[s];
            r.u[1] = accH[s];
            *(float4*)(out + (((size_t)b * 16 + oc) * 252 + p) * 252 + q0) = r.f;
        }
    }
}

__global__ __launch_bounds__(256, 3)
void c3_kernel(const float* __restrict__ x,
               const float* __restrict__ w3, const float* __restrict__ b3,
               const float* __restrict__ w4, const float* __restrict__ b4,
               const float* __restrict__ w6, const float* __restrict__ b6,
               float* __restrict__ out)
{
    // Dup-packed weights: [c][j][ky] rows of 5 (w,w) pairs padded to 12
    // floats (48B): LDS.128 + LDS.128 + LDS.64, immediate offsets.
    __shared__ __align__(16) float wsm[6 * 10 * 5 * 12];
    __shared__ float bsm[16];

    const int tid = (threadIdx.z * 2 + threadIdx.y) * 64 + threadIdx.x;

    for (int idx = tid; idx < 1500; idx += 256) {
        int kx = idx % 5;
        int t  = idx / 5;
        int ky = t % 5;  t /= 5;
        int j  = t % 10;
        int c  = t / 10;
        int off = POFF[c][j] + ky * 5 + kx;
        float w = (off < 450) ? w3[off]
                : (off < 1350) ? w4[off - 450]
                               : w6[off - 1350];
        int d = ((c * 10 + j) * 5 + ky) * 12 + kx * 2;
        wsm[d]     = w;
        wsm[d + 1] = w;
    }
    if (tid < 16) {
        bsm[tid] = (tid < 6) ? b3[tid] : (tid < 15) ? b4[tid - 6] : b6[0];
    }
    __syncthreads();

    const int b  = blockIdx.z;
    const int p  = blockIdx.y * 2 + threadIdx.y;   // output row, 0..251
    const int q0 = threadIdx.x * 4;                // output col base
    const int ql = (q0 > 248) ? 248 : q0;          // tx=63 duplicates tx=62

    if (threadIdx.z == 0)
        compute_group<0>(x, out, wsm, bsm, b, p, q0, ql);
    else
        compute_group<1>(x, out, wsm, bsm, b, p, q0, ql);
}

extern "C" void kernel_launch(void* const* d_in, const int* in_sizes, int n_in,
                              void* d_out, int out_size)
{
    const float* x  = (const float*)d_in[0];
    const float* w3 = (const float*)d_in[1];
    const float* b3 = (const float*)d_in[2];
    const float* w4 = (const float*)d_in[3];
    const float* b4 = (const float*)d_in[4];
    const float* w6 = (const float*)d_in[5];
    const float* b6 = (const float*)d_in[6];
    float* out = (float*)d_out;

    dim3 block(64, 2, 2);        // x: 64 col-tiles, y: 2 rows, z: oc group
    dim3 grid(1, 126, 128);      // 126*2 = 252 rows, 128 batch
    c3_kernel<<<grid, block>>>(x, w3, b3, w4, b4, w6, b6, out);
}

// round 5
// speedup vs baseline: 1.3876x; 1.3876x over previous
#include <cuda_runtime.h>
#include <cstdint>

// ---------------------------------------------------------------------------
// C3 layer: x(128,6,256,256) -> out(128,16,252,252), 5x5 VALID convs.
// Direct conv: 4 horizontal pixels x all 16 output channels per thread.
// Pure scalar fp32 FFMA (no f32x2 packing): on sm_103a the fma AND alu pipes
// both execute the FFMA class at rt2 each -> 1 FFMA/cyc/SMSP sustained, and
// scalar code avoids the register-pair MOV overhead that f32x2 asm forced.
// Weights in smem, 5-float rows padded to 8 (32B) -> LDS.128 + LDS.32 at
// immediate offsets.
// ---------------------------------------------------------------------------

__device__ constexpr int POC[6][10] = {
    {0, 4, 5, 6,  9, 10, 11, 12, 14, 15},
    {0, 1, 5, 6,  7, 10, 11, 12, 13, 15},
    {0, 1, 2, 6,  7,  8, 11, 13, 14, 15},
    {1, 2, 3, 6,  7,  8,  9, 12, 14, 15},
    {2, 3, 4, 7,  8,  9, 10, 12, 13, 15},
    {3, 4, 5, 8,  9, 10, 11, 13, 14, 15}
};
__device__ constexpr int POFF[6][10] = {
    {  0, 300, 375, 450, 750,  850,  950, 1050, 1250, 1350},
    { 25,  75, 400, 475, 550,  875,  975, 1075, 1150, 1375},
    { 50, 100, 150, 500, 575,  650, 1000, 1175, 1275, 1400},
    {125, 175, 225, 525, 600,  675,  775, 1100, 1300, 1425},
    {200, 250, 325, 625, 700,  800,  900, 1125, 1200, 1450},
    {275, 350, 425, 725, 825,  925, 1025, 1225, 1325, 1475}
};

__global__ __launch_bounds__(256, 2)
void c3_kernel(const float* __restrict__ x,
               const float* __restrict__ w3, const float* __restrict__ b3,
               const float* __restrict__ w4, const float* __restrict__ b4,
               const float* __restrict__ w6, const float* __restrict__ b6,
               float* __restrict__ out)
{
    // Weight rows [c][j][ky][0..4], padded to 8 floats (32B).
    __shared__ __align__(16) float wsm[6 * 10 * 5 * 8];
    __shared__ float bsm[16];

    const int tid = threadIdx.y * 64 + threadIdx.x;

    for (int idx = tid; idx < 1500; idx += 256) {
        int kx = idx % 5;
        int t  = idx / 5;
        int ky = t % 5;  t /= 5;
        int j  = t % 10;
        int c  = t / 10;
        int off = POFF[c][j] + ky * 5 + kx;
        float w = (off < 450) ? w3[off]
                : (off < 1350) ? w4[off - 450]
                               : w6[off - 1350];
        wsm[(((c * 10 + j) * 5 + ky) * 8) + kx] = w;
    }
    if (tid < 16) {
        bsm[tid] = (tid < 6) ? b3[tid] : (tid < 15) ? b4[tid - 6] : b6[0];
    }
    __syncthreads();

    const int b  = blockIdx.z;
    const int p  = blockIdx.y * 4 + threadIdx.y;   // output row, 0..251
    const int q0 = threadIdx.x * 4;                // output col base
    const int ql = (q0 > 248) ? 248 : q0;          // tx=63 duplicates tx=62

    // 16 oc x 4 px accumulators in plain fp32 registers.
    float acc[16][4];
    #pragma unroll
    for (int oc = 0; oc < 16; ++oc) {
        float bv = bsm[oc];
        acc[oc][0] = bv; acc[oc][1] = bv; acc[oc][2] = bv; acc[oc][3] = bv;
    }

    #pragma unroll
    for (int c = 0; c < 6; ++c) {
        const float* xp = x + (((size_t)b * 6 + c) * 256 + p) * 256 + ql;
        #pragma unroll
        for (int ky = 0; ky < 5; ++ky) {
            float4 a0 = *(const float4*)(xp + ky * 256);
            float4 a1 = *(const float4*)(xp + ky * 256 + 4);
            float v[8] = {a0.x, a0.y, a0.z, a0.w, a1.x, a1.y, a1.z, a1.w};

            #pragma unroll
            for (int j = 0; j < 10; ++j) {
                const int oc   = POC[c][j];
                const int base = ((c * 10 + j) * 5 + ky) * 8;
                float4 wv = *(const float4*)&wsm[base];
                float  w4v = wsm[base + 4];

                #pragma unroll
                for (int px = 0; px < 4; ++px) {
                    float s = acc[oc][px];
                    s = wv.x  * v[px]     + s;
                    s = wv.y  * v[px + 1] + s;
                    s = wv.z  * v[px + 2] + s;
                    s = wv.w  * v[px + 3] + s;
                    s = w4v   * v[px + 4] + s;
                    acc[oc][px] = s;
                }
            }
        }
    }

    if (q0 < 252) {
        #pragma unroll
        for (int oc = 0; oc < 16; ++oc) {
            float4 r;
            r.x = acc[oc][0]; r.y = acc[oc][1];
            r.z = acc[oc][2]; r.w = acc[oc][3];
            *(float4*)(out + (((size_t)b * 16 + oc) * 252 + p) * 252 + q0) = r;
        }
    }
}

extern "C" void kernel_launch(void* const* d_in, const int* in_sizes, int n_in,
                              void* d_out, int out_size)
{
    const float* x  = (const float*)d_in[0];
    const float* w3 = (const float*)d_in[1];
    const float* b3 = (const float*)d_in[2];
    const float* w4 = (const float*)d_in[3];
    const float* b4 = (const float*)d_in[4];
    const float* w6 = (const float*)d_in[5];
    const float* b6 = (const float*)d_in[6];
    float* out = (float*)d_out;

    dim3 block(64, 4, 1);
    dim3 grid(1, 63, 128);      // 63*4 = 252 rows, 128 batch
    c3_kernel<<<grid, block>>>(x, w3, b3, w4, b4, w6, b6, out);
}